// round 3
// baseline (speedup 1.0000x reference)
#include <cuda_runtime.h>
#include <cstdint>

#define N_NODES 100000
#define D_FEAT  64

// Scratch (allocation-free rule: __device__ globals)
__device__ float g_x1 [N_NODES * D_FEAT];   // 25.6 MB
__device__ float g_sum[N_NODES * D_FEAT];   // 25.6 MB
__device__ float g_deg[N_NODES];            // 400 KB
__device__ int   g_is64;                    // edge-index dtype flag

// ---------------------------------------------------------------------------
// Probe the edge-index dtype. If the first 16 values interpreted as int64 are
// all valid node ids, the buffer is int64; otherwise it is int32 (packed
// pairs give huge values). Deterministic for fixed input.
// ---------------------------------------------------------------------------
__global__ void probe_kernel(const long long* __restrict__ ei) {
    if (threadIdx.x == 0 && blockIdx.x == 0) {
        int ok64 = 1;
        #pragma unroll
        for (int i = 0; i < 16; i++) {
            long long v = ei[i];
            if (v < 0 || v >= N_NODES) ok64 = 0;
        }
        g_is64 = ok64;
    }
}

// ---------------------------------------------------------------------------
// Zero the accumulators.
// ---------------------------------------------------------------------------
__global__ void zero_kernel() {
    int total = N_NODES * D_FEAT + N_NODES;
    for (int i = blockIdx.x * blockDim.x + threadIdx.x; i < total;
         i += gridDim.x * blockDim.x) {
        if (i < N_NODES * D_FEAT) g_sum[i] = 0.0f;
        else                      g_deg[i - N_NODES * D_FEAT] = 0.0f;
    }
}

// ---------------------------------------------------------------------------
// Scatter pass: 16 threads per edge, each handles one float4 chunk of the
// 64-float row. Gather source row (coalesced 256B per edge) and
// red.global.add.v4.f32 into g_sum[dst]. Optionally counts degree (pass 1).
// USE_X1 selects the gather source INSIDE device code (a __device__ global
// cannot be passed as a kernel argument from host — that yields the host-side
// shadow address, which on GB300/ATS reads as zeros instead of faulting).
// ---------------------------------------------------------------------------
template <bool COUNT_DEG, bool USE_X1>
__global__ __launch_bounds__(256)
void scatter_kernel(const float* __restrict__ h_in,
                    const void* __restrict__ edge_buf,
                    int n_edges) {
    long long t = (long long)blockIdx.x * blockDim.x + threadIdx.x;
    int e = (int)(t >> 4);
    int c = (int)(t & 15);
    if (e >= n_edges) return;

    int s, d;
    if (g_is64) {
        const long long* ei = (const long long*)edge_buf;
        s = (int)ei[e];
        d = (int)ei[e + n_edges];
    } else {
        const int* ei = (const int*)edge_buf;
        s = ei[e];
        d = ei[e + n_edges];
    }

    const float* h = USE_X1 ? (const float*)g_x1 : h_in;
    float4 v = __ldg((const float4*)(h + (size_t)s * D_FEAT) + c);

    float* p = &g_sum[(size_t)d * D_FEAT + c * 4];
    asm volatile("red.global.add.v4.f32 [%0], {%1, %2, %3, %4};"
                 :: "l"(p), "f"(v.x), "f"(v.y), "f"(v.z), "f"(v.w)
                 : "memory");

    if (COUNT_DEG && c == 0) {
        atomicAdd(&g_deg[d], 1.0f);
    }
}

// ---------------------------------------------------------------------------
// Normalize: x1 = (deg > 0) ? sum / deg : 0, and re-zero sum for pass 2.
// ---------------------------------------------------------------------------
__global__ __launch_bounds__(256)
void normalize_kernel() {
    int i = blockIdx.x * blockDim.x + threadIdx.x;
    if (i >= N_NODES * D_FEAT) return;
    int node = i >> 6;
    float dg = g_deg[node];
    float sv = g_sum[i];
    g_x1[i]  = (dg > 0.0f) ? (sv / dg) : 0.0f;
    g_sum[i] = 0.0f;
}

// ---------------------------------------------------------------------------
// Final: x2 = (deg>0) ? sum/deg : 0 ; cos(x1,x2) gated blend.
// One warp per node; each lane holds a float2 (64 floats = 32 lanes * 2).
// ---------------------------------------------------------------------------
__global__ __launch_bounds__(256)
void final_kernel(float* __restrict__ out) {
    int node = blockIdx.x * (blockDim.x >> 5) + (threadIdx.x >> 5);
    int lane = threadIdx.x & 31;
    if (node >= N_NODES) return;

    float dg  = g_deg[node];
    float inv = (dg > 0.0f) ? (1.0f / dg) : 0.0f;

    const float2* s2  = (const float2*)g_sum;
    const float2* x12 = (const float2*)g_x1;
    size_t idx = (size_t)node * 32 + lane;

    float2 s  = s2[idx];
    float2 x2 = make_float2(s.x * inv, s.y * inv);
    float2 x1 = x12[idx];

    float dot  = x1.x * x2.x + x1.y * x2.y;
    float n1sq = x1.x * x1.x + x1.y * x1.y;
    float n2sq = x2.x * x2.x + x2.y * x2.y;

    #pragma unroll
    for (int o = 16; o > 0; o >>= 1) {
        dot  += __shfl_xor_sync(0xFFFFFFFFu, dot,  o);
        n1sq += __shfl_xor_sync(0xFFFFFFFFu, n1sq, o);
        n2sq += __shfl_xor_sync(0xFFFFFFFFu, n2sq, o);
    }

    float w = dot / fmaxf(sqrtf(n1sq) * sqrtf(n2sq), 1e-8f);

    float2 o2;
    o2.x = w * x2.x + (1.0f - w) * x1.x;
    o2.y = w * x2.y + (1.0f - w) * x1.y;
    ((float2*)out)[idx] = o2;
}

// ---------------------------------------------------------------------------
// Launch
// ---------------------------------------------------------------------------
extern "C" void kernel_launch(void* const* d_in, const int* in_sizes, int n_in,
                              void* d_out, int out_size) {
    const float* features = (const float*)d_in[0];
    const void*  edge_buf = d_in[1];
    int n_edges = in_sizes[1] / 2;

    // 0. detect edge-index dtype (int32 vs int64)
    probe_kernel<<<1, 32>>>((const long long*)edge_buf);

    // 1. zero accumulators
    zero_kernel<<<1024, 256>>>();

    // 2. pass 1: sum features[src] into sum[dst], count degree
    long long work = (long long)n_edges * 16;
    int blocks = (int)((work + 255) / 256);
    scatter_kernel<true, false><<<blocks, 256>>>(features, edge_buf, n_edges);

    // 3. x1 = sum/deg, re-zero sum
    normalize_kernel<<<(N_NODES * D_FEAT + 255) / 256, 256>>>();

    // 4. pass 2: sum x1[src] into sum[dst] (source = g_x1, bound in device code)
    scatter_kernel<false, true><<<blocks, 256>>>(nullptr, edge_buf, n_edges);

    // 5. x2 = sum/deg, cosine blend, write output
    final_kernel<<<(N_NODES + 7) / 8, 256>>>((float*)d_out);
}

// round 4
// speedup vs baseline: 1.0631x; 1.0631x over previous
#include <cuda_runtime.h>
#include <cstdint>

#define N_NODES 100000
#define D_FEAT  64

// Scratch (allocation-free rule: __device__ globals)
__device__ float g_sum [N_NODES * D_FEAT];  // pass-1 accumulator (25.6 MB)
__device__ float g_sum2[N_NODES * D_FEAT];  // pass-2 accumulator (25.6 MB)
__device__ float g_deg [N_NODES];           // degree
__device__ float g_inv [N_NODES];           // 1/deg (0 if deg==0)
__device__ int   g_is64;                    // edge-index dtype flag

// ---------------------------------------------------------------------------
// Prep: zero both accumulators (float4 stores) + degree, and probe the
// edge-index dtype (int64 vs int32) from block 0.
// ---------------------------------------------------------------------------
__global__ __launch_bounds__(256)
void prep_kernel(const long long* __restrict__ ei) {
    if (blockIdx.x == 0 && threadIdx.x == 0) {
        int ok64 = 1;
        #pragma unroll
        for (int i = 0; i < 16; i++) {
            long long v = ei[i];
            if (v < 0 || v >= N_NODES) ok64 = 0;
        }
        g_is64 = ok64;
    }

    const int n4 = N_NODES * D_FEAT / 4;          // 1.6M float4 per buffer
    float4 z = make_float4(0.f, 0.f, 0.f, 0.f);
    float4* s1 = (float4*)g_sum;
    float4* s2 = (float4*)g_sum2;
    for (int i = blockIdx.x * blockDim.x + threadIdx.x; i < n4;
         i += gridDim.x * blockDim.x) {
        s1[i] = z;
        s2[i] = z;
    }
    for (int i = blockIdx.x * blockDim.x + threadIdx.x; i < N_NODES;
         i += gridDim.x * blockDim.x) {
        g_deg[i] = 0.0f;
    }
}

// ---------------------------------------------------------------------------
// Scatter pass: 16 threads per edge, each handles one float4 chunk of the
// 64-float row. PASS1: gather features[src], red into g_sum, count degree.
// PASS2: gather g_sum[src] * g_inv[src]  (i.e. x1[src], never materialized),
// red into g_sum2.
// NOTE: __device__ globals must be referenced in device code, never passed
// as kernel args from host (host shadow address reads as zeros via ATS).
// ---------------------------------------------------------------------------
template <bool PASS1>
__global__ __launch_bounds__(256)
void scatter_kernel(const float* __restrict__ h_in,
                    const void* __restrict__ edge_buf,
                    int n_edges) {
    long long t = (long long)blockIdx.x * blockDim.x + threadIdx.x;
    int e = (int)(t >> 4);
    int c = (int)(t & 15);
    if (e >= n_edges) return;

    int s, d;
    if (g_is64) {
        const long long* ei = (const long long*)edge_buf;
        s = (int)ei[e];
        d = (int)ei[e + n_edges];
    } else {
        const int* ei = (const int*)edge_buf;
        s = ei[e];
        d = ei[e + n_edges];
    }

    float4 v;
    if (PASS1) {
        v = __ldg((const float4*)(h_in + (size_t)s * D_FEAT) + c);
    } else {
        float inv = __ldg(&g_inv[s]);
        v = __ldg((const float4*)((const float*)g_sum + (size_t)s * D_FEAT) + c);
        v.x *= inv; v.y *= inv; v.z *= inv; v.w *= inv;
    }

    float* acc = PASS1 ? (float*)g_sum : (float*)g_sum2;
    float* p = acc + (size_t)d * D_FEAT + c * 4;
    asm volatile("red.global.add.v4.f32 [%0], {%1, %2, %3, %4};"
                 :: "l"(p), "f"(v.x), "f"(v.y), "f"(v.z), "f"(v.w)
                 : "memory");

    if (PASS1 && c == 0) {
        atomicAdd(&g_deg[d], 1.0f);
    }
}

// ---------------------------------------------------------------------------
// inv_deg = deg > 0 ? 1/deg : 0
// ---------------------------------------------------------------------------
__global__ __launch_bounds__(256)
void inv_kernel() {
    int i = blockIdx.x * blockDim.x + threadIdx.x;
    if (i >= N_NODES) return;
    float dg = g_deg[i];
    g_inv[i] = (dg > 0.0f) ? (1.0f / dg) : 0.0f;
}

// ---------------------------------------------------------------------------
// Final: x1 = sum*inv, x2 = sum2*inv, cos(x1,x2)-gated blend.
// One warp per node; each lane holds a float2 (64 floats = 32 lanes * 2).
// ---------------------------------------------------------------------------
__global__ __launch_bounds__(256)
void final_kernel(float* __restrict__ out) {
    int node = blockIdx.x * (blockDim.x >> 5) + (threadIdx.x >> 5);
    int lane = threadIdx.x & 31;
    if (node >= N_NODES) return;

    float inv = g_inv[node];

    const float2* s1 = (const float2*)g_sum;
    const float2* s2 = (const float2*)g_sum2;
    size_t idx = (size_t)node * 32 + lane;

    float2 a = s1[idx];
    float2 b = s2[idx];
    float2 x1 = make_float2(a.x * inv, a.y * inv);
    float2 x2 = make_float2(b.x * inv, b.y * inv);

    float dot  = x1.x * x2.x + x1.y * x2.y;
    float n1sq = x1.x * x1.x + x1.y * x1.y;
    float n2sq = x2.x * x2.x + x2.y * x2.y;

    #pragma unroll
    for (int o = 16; o > 0; o >>= 1) {
        dot  += __shfl_xor_sync(0xFFFFFFFFu, dot,  o);
        n1sq += __shfl_xor_sync(0xFFFFFFFFu, n1sq, o);
        n2sq += __shfl_xor_sync(0xFFFFFFFFu, n2sq, o);
    }

    float w = dot / fmaxf(sqrtf(n1sq) * sqrtf(n2sq), 1e-8f);

    float2 o2;
    o2.x = w * x2.x + (1.0f - w) * x1.x;
    o2.y = w * x2.y + (1.0f - w) * x1.y;
    ((float2*)out)[idx] = o2;
}

// ---------------------------------------------------------------------------
// Launch
// ---------------------------------------------------------------------------
extern "C" void kernel_launch(void* const* d_in, const int* in_sizes, int n_in,
                              void* d_out, int out_size) {
    const float* features = (const float*)d_in[0];
    const void*  edge_buf = d_in[1];
    int n_edges = in_sizes[1] / 2;

    // 1. zero accumulators + degree, probe edge dtype
    prep_kernel<<<2048, 256>>>((const long long*)edge_buf);

    // 2. pass 1: sum features[src] into g_sum[dst], count degree
    long long work = (long long)n_edges * 16;
    int blocks = (int)((work + 255) / 256);
    scatter_kernel<true><<<blocks, 256>>>(features, edge_buf, n_edges);

    // 3. inv_deg
    inv_kernel<<<(N_NODES + 255) / 256, 256>>>();

    // 4. pass 2: sum x1[src] (= g_sum[src]*inv[src]) into g_sum2[dst]
    scatter_kernel<false><<<blocks, 256>>>(nullptr, edge_buf, n_edges);

    // 5. x1/x2 normalize + cosine blend, write output
    final_kernel<<<(N_NODES + 7) / 8, 256>>>((float*)d_out);
}